// round 3
// baseline (speedup 1.0000x reference)
#include <cuda_runtime.h>
#include <math.h>

#define NA 900
#define NC 6
#define NL 4
#define NPTS 13
#define ED 256
#define NG 8
#define SS (NC*NL*NPTS)   /* 312 */
#define JJ (NL*NPTS*NG)   /* 416 */

// Level geometry
// pixels per cam per level: 64*176=11264, 32*88=2816, 16*44=704, 8*22=176
// cam-major-within-level pixel bases: 0, 6*11264=67584, 84480, 88704 ; total 89760
#define TOT_PIX 89760

// ---------------- scratch (device globals; no runtime allocation) ----------------
__device__ float  g_fmapT[TOT_PIX * ED];       // ~92 MB channel-last feature maps
__device__ float  g_grid[NA * NC * NPTS * 2];  // normalized grid coords
__device__ float  g_ce[NC * ED];               // camera embeddings
__device__ float  g_B[NC * JJ];                // cam_embed @ wfc_w + b
__device__ float  g_A[NA * JJ];                // feat @ wfc_w
__device__ float  g_sw[NA * SS * NG];          // softmaxed weights
__device__ int4   g_si[NA * SS];               // 4 corner element indices (pixel*256)
__device__ float4 g_swt[NA * SS];              // 4 corner bilinear weights (validity folded)

// ---------------- kernel 1: transpose fmap (C,ED,H,W) -> channel-last ----------------
__global__ void k_transpose(const float* __restrict__ src, int P, int basePix) {
    __shared__ float tile[32][33];
    int cam = blockIdx.z;
    int p0 = blockIdx.x * 32;
    int d0 = blockIdx.y * 32;
    int tx = threadIdx.x, ty = threadIdx.y;
#pragma unroll
    for (int i = ty; i < 32; i += 8) {
        int p = p0 + tx;
        if (p < P) tile[i][tx] = src[((size_t)cam * ED + d0 + i) * P + p];
    }
    __syncthreads();
#pragma unroll
    for (int i = ty; i < 32; i += 8) {
        int p = p0 + i;
        if (p < P) g_fmapT[((size_t)(basePix + cam * P + p)) * ED + d0 + tx] = tile[tx][i];
    }
}

// ---------------- LN helper (256 threads) ----------------
__device__ __forceinline__ float ln256(float x, float g, float b, float* red) {
    float s = x;
#pragma unroll
    for (int o = 16; o > 0; o >>= 1) s += __shfl_xor_sync(0xffffffffu, s, o);
    if ((threadIdx.x & 31) == 0) red[threadIdx.x >> 5] = s;
    __syncthreads();
    if (threadIdx.x == 0) { float t = 0.f; for (int i = 0; i < 8; i++) t += red[i]; red[0] = t; }
    __syncthreads();
    float mean = red[0] * (1.f / 256.f);
    __syncthreads();
    float d = x - mean;
    float q = d * d;
#pragma unroll
    for (int o = 16; o > 0; o >>= 1) q += __shfl_xor_sync(0xffffffffu, q, o);
    if ((threadIdx.x & 31) == 0) red[threadIdx.x >> 5] = q;
    __syncthreads();
    if (threadIdx.x == 0) { float t = 0.f; for (int i = 0; i < 8; i++) t += red[i]; red[0] = t; }
    __syncthreads();
    float var = red[0] * (1.f / 256.f);
    float r = d * rsqrtf(var + 1e-5f) * g + b;
    __syncthreads();
    return r;
}

// ---------------- kernel 2: camera embedding MLP (6 blocks x 256 thr) ----------------
__global__ void k_cam(const float* __restrict__ proj,
                      const float* __restrict__ w1, const float* __restrict__ b1,
                      const float* __restrict__ g1, const float* __restrict__ be1,
                      const float* __restrict__ w2, const float* __restrict__ b2,
                      const float* __restrict__ g2, const float* __restrict__ be2) {
    int c = blockIdx.x, j = threadIdx.x;
    __shared__ float cin[12];
    __shared__ float h[ED];
    __shared__ float red[8];
    if (j < 12) cin[j] = proj[c * 16 + j];
    __syncthreads();
    float v = b1[j];
#pragma unroll
    for (int k = 0; k < 12; k++) v = fmaf(cin[k], w1[k * ED + j], v);
    v = fmaxf(v, 0.f);
    v = ln256(v, g1[j], be1[j], red);
    h[j] = v;
    __syncthreads();
    float u = b2[j];
#pragma unroll 8
    for (int k = 0; k < ED; k++) u = fmaf(h[k], w2[k * ED + j], u);
    u = fmaxf(u, 0.f);
    u = ln256(u, g2[j], be2[j], red);
    g_ce[c * ED + j] = u;
}

// ---------------- kernel 3: keypoints + projection -> normalized grid ----------------
__global__ void k_keyproj(const float* __restrict__ inst, const float* __restrict__ anchor,
                          const float* __restrict__ lfcw, const float* __restrict__ lfcb,
                          const float* __restrict__ proj, const float* __restrict__ imwh,
                          const float* __restrict__ fixs) {
    int n = blockIdx.x, t = threadIdx.x;
    __shared__ float f[ED];
    __shared__ float ls[18];
    __shared__ float kp[13][3];
    __shared__ float anc[11];
    f[t] = inst[n * ED + t];
    if (t < 11) anc[t] = anchor[n * 11 + t];
    __syncthreads();
    if (t < 18) {
        float v = lfcb[t];
#pragma unroll 8
        for (int k = 0; k < ED; k++) v = fmaf(f[k], lfcw[k * 18 + t], v);
        ls[t] = 1.f / (1.f + expf(-v)) - 0.5f;
    }
    __syncthreads();
    if (t < 13) {
        float sx = expf(anc[3]), sy = expf(anc[4]), sz = expf(anc[5]);
        float kx, ky, kz;
        if (t < 7) { kx = fixs[t * 3] * sx; ky = fixs[t * 3 + 1] * sy; kz = fixs[t * 3 + 2] * sz; }
        else { int r = t - 7; kx = ls[r * 3] * sx; ky = ls[r * 3 + 1] * sy; kz = ls[r * 3 + 2] * sz; }
        float sn = anc[6], cs = anc[7];
        kp[t][0] = cs * kx - sn * ky + anc[0];
        kp[t][1] = sn * kx + cs * ky + anc[1];
        kp[t][2] = kz + anc[2];
    }
    __syncthreads();
    if (t < NC * NPTS) {
        int c = t / NPTS, p = t % NPTS;
        const float* P = proj + c * 16;
        float x = kp[p][0], y = kp[p][1], z = kp[p][2];
        float r0 = P[0] * x + P[1] * y + P[2] * z + P[3];
        float r1 = P[4] * x + P[5] * y + P[6] * z + P[7];
        float r2 = P[8] * x + P[9] * y + P[10] * z + P[11];
        float zz = fmaxf(r2, 1e-5f);
        float gx = (r0 / zz) / imwh[c * 2] * 2.f - 1.f;
        float gy = (r1 / zz) / imwh[c * 2 + 1] * 2.f - 1.f;
        g_grid[((n * NC + c) * NPTS + p) * 2]     = gx;
        g_grid[((n * NC + c) * NPTS + p) * 2 + 1] = gy;
    }
}

// ---------------- kernel 4: B[c][j] = cam_embed[c] @ wfc_w + wfc_b ----------------
__global__ void k_camB(const float* __restrict__ wfcw, const float* __restrict__ wfcb) {
    int c = blockIdx.x, j = threadIdx.x;  // 416 threads
    __shared__ float s[ED];
    if (j < ED) s[j] = g_ce[c * ED + j];
    __syncthreads();
    float v = wfcb[j];
#pragma unroll 8
    for (int k = 0; k < ED; k++) v = fmaf(s[k], wfcw[k * JJ + j], v);
    g_B[c * JJ + j] = v;
}

// ---------------- kernel 5: A[n][j] = (inst+anchor_embed)[n] @ wfc_w ----------------
#define AB 10
__global__ void k_A(const float* __restrict__ inst, const float* __restrict__ aemb,
                    const float* __restrict__ wfcw) {
    int n0 = blockIdx.x * AB; int j = threadIdx.x;  // 416 threads
    __shared__ float fs[AB][ED];
    for (int i = j; i < AB * ED; i += blockDim.x) {
        int a = i >> 8, k = i & 255;
        fs[a][k] = inst[(n0 + a) * ED + k] + aemb[(n0 + a) * ED + k];
    }
    __syncthreads();
    float acc[AB];
#pragma unroll
    for (int a = 0; a < AB; a++) acc[a] = 0.f;
    for (int k = 0; k < ED; k++) {
        float w = wfcw[k * JJ + j];
#pragma unroll
        for (int a = 0; a < AB; a++) acc[a] = fmaf(fs[a][k], w, acc[a]);
    }
#pragma unroll
    for (int a = 0; a < AB; a++) g_A[(n0 + a) * JJ + j] = acc[a];
}

// ---------------- kernel 6: bilinear sample params per (n,c,l,p) ----------------
__global__ void k_samp() {
    int idx = blockIdx.x * blockDim.x + threadIdx.x;
    if (idx >= NA * SS) return;
    int n = idx / SS, s = idx - n * SS;
    int c = s / (NL * NPTS); int r = s - c * (NL * NPTS);
    int l = r / NPTS, p = r - l * NPTS;
    const int Hs[4] = {64, 32, 16, 8}, Ws[4] = {176, 88, 44, 22};
    const int base[4] = {0, 67584, 84480, 88704};
    float gxn = g_grid[((n * NC + c) * NPTS + p) * 2];
    float gyn = g_grid[((n * NC + c) * NPTS + p) * 2 + 1];
    int H = Hs[l], W = Ws[l];
    float gx = fminf(fmaxf((gxn + 1.f) * (W * 0.5f) - 0.5f, -10000.f), 10000.f);
    float gy = fminf(fmaxf((gyn + 1.f) * (H * 0.5f) - 0.5f, -10000.f), 10000.f);
    float x0f = floorf(gx), y0f = floorf(gy);
    float wx1 = gx - x0f, wy1 = gy - y0f;
    float wx0 = 1.f - wx1, wy0 = 1.f - wy1;
    int x0 = (int)x0f, y0 = (int)y0f;
    int x1 = x0 + 1, y1 = y0 + 1;
    bool vx0 = (x0 >= 0 && x0 < W), vx1 = (x1 >= 0 && x1 < W);
    bool vy0 = (y0 >= 0 && y0 < H), vy1 = (y1 >= 0 && y1 < H);
    int cx0 = min(max(x0, 0), W - 1), cx1 = min(max(x1, 0), W - 1);
    int cy0 = min(max(y0, 0), H - 1), cy1 = min(max(y1, 0), H - 1);
    int pb = base[l] + c * H * W;
    int4 ii;
    ii.x = (pb + cy0 * W + cx0) * ED;
    ii.y = (pb + cy0 * W + cx1) * ED;
    ii.z = (pb + cy1 * W + cx0) * ED;
    ii.w = (pb + cy1 * W + cx1) * ED;
    float4 ww;
    ww.x = wx0 * wy0 * (float)(vx0 && vy0);
    ww.y = wx1 * wy0 * (float)(vx1 && vy0);
    ww.z = wx0 * wy1 * (float)(vx0 && vy1);
    ww.w = wx1 * wy1 * (float)(vx1 && vy1);
    g_si[idx] = ii;
    g_swt[idx] = ww;
}

// ---------------- kernel 7: softmax over 312 per (n,g) ----------------
__global__ void k_softmax() {
    int n = blockIdx.x;
    int g = threadIdx.x >> 5, lane = threadIdx.x & 31;
    float v[10];
    float mx = -1e30f;
#pragma unroll
    for (int i = 0; i < 10; i++) {
        int s = lane + i * 32;
        if (s < SS) {
            int c = s / (NL * NPTS); int r = s - c * (NL * NPTS);
            float val = g_A[n * JJ + r * 8 + g] + g_B[c * JJ + r * 8 + g];
            v[i] = val; mx = fmaxf(mx, val);
        } else v[i] = -1e30f;
    }
#pragma unroll
    for (int o = 16; o > 0; o >>= 1) mx = fmaxf(mx, __shfl_xor_sync(0xffffffffu, mx, o));
    float sum = 0.f;
#pragma unroll
    for (int i = 0; i < 10; i++) {
        v[i] = expf(v[i] - mx);
        if (lane + i * 32 < SS) sum += v[i];
    }
#pragma unroll
    for (int o = 16; o > 0; o >>= 1) sum += __shfl_xor_sync(0xffffffffu, sum, o);
    float inv = 1.f / sum;
#pragma unroll
    for (int i = 0; i < 10; i++) {
        int s = lane + i * 32;
        if (s < SS) g_sw[(n * SS + s) * NG + g] = v[i] * inv;
    }
}

// ---------------- kernel 8: gather+fuse + final GEMM + concat ----------------
__global__ void __launch_bounds__(256) k_fuse(const float* __restrict__ opw,
                                              const float* __restrict__ opb,
                                              const float* __restrict__ inst,
                                              float* __restrict__ out) {
    int n = blockIdx.x, t = threadIdx.x, g = t >> 5;
    __shared__ float  s_w[SS * NG];
    __shared__ int4   s_i[SS];
    __shared__ float4 s_v[SS];
    __shared__ float  fused[ED];
    for (int i = t; i < SS * NG; i += 256) s_w[i] = g_sw[n * SS * NG + i];
    for (int i = t; i < SS; i += 256) { s_i[i] = g_si[n * SS + i]; s_v[i] = g_swt[n * SS + i]; }
    __syncthreads();
    float acc = 0.f;
#pragma unroll 4
    for (int s = 0; s < SS; s++) {
        float w = s_w[s * NG + g];
        int4 ii = s_i[s]; float4 ww = s_v[s];
        float v;
        v = ww.x * g_fmapT[ii.x + t];
        v = fmaf(ww.y, g_fmapT[ii.y + t], v);
        v = fmaf(ww.z, g_fmapT[ii.z + t], v);
        v = fmaf(ww.w, g_fmapT[ii.w + t], v);
        acc = fmaf(w, v, acc);
    }
    fused[t] = acc;
    __syncthreads();
    float o = opb[t];
#pragma unroll 8
    for (int k = 0; k < ED; k++) o = fmaf(fused[k], opw[k * ED + t], o);
    out[(size_t)n * 2 * ED + t] = o;
    out[(size_t)n * 2 * ED + ED + t] = inst[n * ED + t];
}

// ---------------- launch ----------------
extern "C" void kernel_launch(void* const* d_in, const int* in_sizes, int n_in,
                              void* d_out, int out_size) {
    const float* inst  = (const float*)d_in[0];
    const float* anch  = (const float*)d_in[1];
    const float* aemb  = (const float*)d_in[2];
    const float* fm0   = (const float*)d_in[3];
    const float* fm1   = (const float*)d_in[4];
    const float* fm2   = (const float*)d_in[5];
    const float* fm3   = (const float*)d_in[6];
    const float* proj  = (const float*)d_in[7];
    const float* imwh  = (const float*)d_in[8];
    const float* fixs  = (const float*)d_in[9];
    const float* lfcw  = (const float*)d_in[10];
    const float* lfcb  = (const float*)d_in[11];
    const float* cw1   = (const float*)d_in[12];
    const float* cb1   = (const float*)d_in[13];
    const float* cg1   = (const float*)d_in[14];
    const float* cbe1  = (const float*)d_in[15];
    const float* cw2   = (const float*)d_in[16];
    const float* cb2   = (const float*)d_in[17];
    const float* cg2   = (const float*)d_in[18];
    const float* cbe2  = (const float*)d_in[19];
    const float* wfcw  = (const float*)d_in[20];
    const float* wfcb  = (const float*)d_in[21];
    const float* opw   = (const float*)d_in[22];
    const float* opb   = (const float*)d_in[23];
    float* out = (float*)d_out;

    dim3 tb(32, 8);
    k_transpose<<<dim3(352, 8, 6), tb>>>(fm0, 11264, 0);
    k_transpose<<<dim3(88,  8, 6), tb>>>(fm1, 2816, 67584);
    k_transpose<<<dim3(22,  8, 6), tb>>>(fm2, 704,  84480);
    k_transpose<<<dim3(6,   8, 6), tb>>>(fm3, 176,  88704);

    k_cam<<<NC, 256>>>(proj, cw1, cb1, cg1, cbe1, cw2, cb2, cg2, cbe2);
    k_keyproj<<<NA, 256>>>(inst, anch, lfcw, lfcb, proj, imwh, fixs);
    k_camB<<<NC, JJ>>>(wfcw, wfcb);
    k_A<<<NA / AB, JJ>>>(inst, aemb, wfcw);
    k_samp<<<(NA * SS + 255) / 256, 256>>>();
    k_softmax<<<NA, 256>>>();
    k_fuse<<<NA, 256>>>(opw, opb, inst, out);
}